// round 16
// baseline (speedup 1.0000x reference)
#include <cuda_runtime.h>
#include <cuda_fp16.h>
#include <math.h>

#define BATCH 8
#define CH    512
#define NPIX  4356          // 66*66 valid pixels
#define SUP   138
#define KTOT  4608
#define PIT   68            // padded-image pitch (cols 64..67 zero)
#define CISZ  (70 * PIT)    // 4760 halves per ci image
#define BSZ   (512 * CISZ)  // per-batch padded image halves
#define MB    4488          // per-batch GEMM M (66*68)
#define MTOT  (BATCH * MB)  // 35904
#define NTILES 281          // ceil(35904/128) = 280.5 -> 281

typedef unsigned int u32;
typedef unsigned long long u64;

// ---------------- scratch (device globals; zero-initialized) ----------------
__device__ float g_styles[BATCH * CH];
__device__ float g_s[BATCH * CH];
__device__ __align__(16) __half g_xp[3 * BATCH * (size_t)BSZ];    // 3 kx-shifted padded imgs
// B weights, chunk-major: [chunk 144][otile 4][o 128][k 32] halves
__device__ __align__(16) __half g_wtB[(size_t)CH * KTOT];
__device__ u32 g_ka[KTOT];                                        // k -> halves offset
__device__ float g_A[CH * CH];
__device__ float g_d[BATCH * CH];
__device__ __align__(16) float g_y[(size_t)BATCH * CH * MB];      // conv out [b][o][p68]

__device__ __forceinline__ void ldsm4(u32& r0, u32& r1, u32& r2, u32& r3, u32 addr) {
    asm volatile("ldmatrix.sync.aligned.m8n8.x4.shared.b16 {%0,%1,%2,%3}, [%4];"
        : "=r"(r0), "=r"(r1), "=r"(r2), "=r"(r3) : "r"(addr));
}
__device__ __forceinline__ void ldsm4t(u32& r0, u32& r1, u32& r2, u32& r3, u32 addr) {
    asm volatile("ldmatrix.sync.aligned.m8n8.x4.trans.shared.b16 {%0,%1,%2,%3}, [%4];"
        : "=r"(r0), "=r"(r1), "=r"(r2), "=r"(r3) : "r"(addr));
}
__device__ __forceinline__ void mma_f16(float* c, u32 a0, u32 a1, u32 a2, u32 a3,
                                        u32 b0, u32 b1) {
    asm volatile("mma.sync.aligned.m16n8k16.row.col.f32.f16.f16.f32 "
        "{%0,%1,%2,%3}, {%4,%5,%6,%7}, {%8,%9}, {%0,%1,%2,%3};"
        : "+f"(c[0]), "+f"(c[1]), "+f"(c[2]), "+f"(c[3])
        : "r"(a0), "r"(a1), "r"(a2), "r"(a3), "r"(b0), "r"(b1));
}
__device__ __forceinline__ u32 smem_u32(const void* p) {
    u32 a; asm("{ .reg .u64 t; cvta.to.shared.u64 t, %1; cvt.u32.u64 %0, t; }"
               : "=r"(a) : "l"(p));
    return a;
}
__device__ __forceinline__ u64 gmem_u64(const void* p) {
    u64 a; asm("cvta.to.global.u64 %0, %1;" : "=l"(a) : "l"(p));
    return a;
}
__device__ __forceinline__ void cpa8(u32 dst, u64 src) {
    asm volatile("cp.async.ca.shared.global [%0], [%1], 8;"
                 :: "r"(dst), "l"(src) : "memory");
}
__device__ __forceinline__ void cpa16(u32 dst, u64 src) {
    asm volatile("cp.async.cg.shared.global [%0], [%1], 16;"
                 :: "r"(dst), "l"(src) : "memory");
}
__device__ __forceinline__ void cpa_commit() {
    asm volatile("cp.async.commit_group;" ::: "memory");
}
template <int N> __device__ __forceinline__ void cpa_wait() {
    asm volatile("cp.async.wait_group %0;" :: "n"(N) : "memory");
}

// ---------------- K1 (merged): wt-normalize + styles + ka table -------------
__global__ void k_pre(const float* __restrict__ cw,
                      const float* __restrict__ w,
                      const float* __restrict__ aw,
                      const float* __restrict__ ab) {
    __shared__ float red[256];
    __shared__ float rsh;
    if (blockIdx.x < 512) {
        int o = blockIdx.x;
        const float* src = cw + (size_t)o * KTOT;
        float ss = 0.f;
        for (int e = threadIdx.x; e < KTOT; e += 256) {
            float v = src[e]; ss = fmaf(v, v, ss);
        }
        red[threadIdx.x] = ss; __syncthreads();
        for (int s = 128; s > 0; s >>= 1) {
            if (threadIdx.x < s) red[threadIdx.x] += red[threadIdx.x + s];
            __syncthreads();
        }
        if (threadIdx.x == 0) rsh = rsqrtf(red[0] * (1.0f / 4608.0f));
        __syncthreads();
        float r = rsh;
        int otile = o >> 7, orow = o & 127;
        for (int e = threadIdx.x; e < KTOT; e += 256) {
            int chunk = e >> 5, kk = e & 31;
            size_t dst = (((size_t)(chunk * 4 + otile) * 128 + orow) << 5) + kk;
            g_wtB[dst] = __float2half_rn(src[e] * r);
        }
        float r2 = r * r;
        for (int i = threadIdx.x; i < 512; i += 256) {
            float s9 = 0.f;
            #pragma unroll
            for (int k = 0; k < 9; k++) { float v = src[i * 9 + k]; s9 = fmaf(v, v, s9); }
            g_A[o * 512 + i] = s9 * r2;
        }
    } else if (blockIdx.x < 1024) {
        int wid = ((blockIdx.x - 512) * 256 + threadIdx.x) >> 5;
        int lane = threadIdx.x & 31;
        int b = wid >> 9, c = wid & 511;
        const float* wr = w + b * 512;
        const float* ar = aw + c * 512;
        float acc = 0.f;
        #pragma unroll 4
        for (int d = lane; d < 512; d += 32) acc = fmaf(wr[d], ar[d], acc);
        #pragma unroll
        for (int s = 16; s; s >>= 1) acc += __shfl_xor_sync(0xFFFFFFFFu, acc, s);
        if (lane == 0) g_styles[wid] = acc * 0.04419417382415922f + ab[c];
    } else {
        int k = (blockIdx.x - 1024) * 256 + threadIdx.x;
        if (k < KTOT) {
            int ci = k / 9; int t9 = k - 9 * ci;
            int ky = t9 / 3; int kx = t9 - 3 * ky;
            g_ka[k] = (u32)kx * (BATCH * (u32)BSZ) + (u32)(ci * CISZ + ky * PIT);
        }
    }
}

// ---------------- K2: normalize styles --------------------------------------
__global__ void k_norm_styles() {
    __shared__ float red[256];
    float ss = 0.f;
    for (int i = threadIdx.x; i < 4096; i += 256) {
        float v = g_styles[i]; ss = fmaf(v, v, ss);
    }
    red[threadIdx.x] = ss; __syncthreads();
    for (int s = 128; s > 0; s >>= 1) {
        if (threadIdx.x < s) red[threadIdx.x] += red[threadIdx.x + s];
        __syncthreads();
    }
    float g = rsqrtf(red[0] * (1.0f / 4096.0f));
    for (int i = threadIdx.x; i < 4096; i += 256) g_s[i] = g_styles[i] * g;
}

// ---------------- K3: one-pass padded+scaled images (pitch 68), 3 shifts -----
// Pfull[ci][rr][cc]: rr in [2,66) & cc<64 -> x[rr-2][cc]*s else 0. 34 pairs/row.
__global__ void k_pad(const float* __restrict__ x) {
    int i2 = blockIdx.x * 256 + threadIdx.x;       // pair index, valid < 2380
    int ci = blockIdx.y, b = blockIdx.z;
    if (i2 >= 2380) return;
    int rr = i2 / 34;            // 0..69
    int cc = 2 * (i2 - rr * 34); // 0..66 even
    float s = g_s[b * 512 + ci];
    bool rok = (rr >= 2) & (rr < 66);
    float v0 = 0.f, v1 = 0.f;
    if (rok && cc < 64) {
        float2 xv = *(const float2*)&x[(((size_t)(b * 512 + ci)) * 64 + (rr - 2)) * 64 + cc];
        v0 = xv.x * s; v1 = xv.y * s;
    }
    float pv = 0.f;
    if (rok && cc > 0 && cc - 1 < 64)
        pv = x[(((size_t)(b * 512 + ci)) * 64 + (rr - 2)) * 64 + (cc - 1)] * s;
    float pv_sh = __shfl_up_sync(0xFFFFFFFFu, v1, 1);
    if ((threadIdx.x & 31) != 0) pv = pv_sh;       // lane>0: Pfull[j-1] via neighbor

    __half2 pair  = __floats2half2_rn(v0, v1);
    __half2 pair1 = __floats2half2_rn(pv, v0);
    int j = 2 * i2;
    u32 base = (u32)(ci * CISZ + j);
    __half2* xp2 = (__half2*)g_xp;
    size_t b2 = ((size_t)b * BSZ) >> 1;
    size_t img = (size_t)BATCH * BSZ >> 1;
    xp2[2 * img + b2 + (base >> 1)] = pair;                 // kx=2 (shift 0)
    if (!(ci == 511 && i2 == 2379))
        xp2[b2 + ((base + 2) >> 1)] = pair;                 // kx=0 (shift -2)
    xp2[img + b2 + (base >> 1)] = pair1;                    // kx=1 (shift -1)
}

// ---------------- K4: fp16 HMMA conv, batch folded into M, 281 tiles ---------
#define ASTG 8704
#define BSTG 10240
#define CONV_SMEM (3 * (ASTG + BSTG))   // 56832

__global__ __launch_bounds__(256, 2) void k_conv() {
    extern __shared__ __align__(16) char dsm[];
    int tid = threadIdx.x, wid = tid >> 5, lane = tid & 31;
    int g = lane >> 2, tg = lane & 3;
    int wm = wid & 3, wn = wid >> 2;
    int p0 = blockIdx.x * 128, o0 = blockIdx.y * 128;

    u32 sb = smem_u32(dsm);
    u32 AsB[3], BsB[3];
    #pragma unroll
    for (int s = 0; s < 3; s++) {
        AsB[s] = sb + s * ASTG;
        BsB[s] = sb + 3 * ASTG + s * BSTG;
    }
    u64 xg = gmem_u64(g_xp);
    u64 wg = gmem_u64(g_wtB) + (u64)((u32)blockIdx.y * 8192u);

    // per-thread A staging coords (fixed across chunks): 4 cpa8 of 4 p-rows
    u32 aoff[4], adst[4];
    int akk[4];
    #pragma unroll
    for (int q = 0; q < 4; q++) {
        int idx = tid + q * 256;
        int kk = idx >> 5, s8 = idx & 31;
        akk[q] = kk;
        adst[q] = (u32)(kk * 272 + s8 * 8);
        u32 gp = (u32)p0 + (u32)(s8 * 4);
        u32 bb = gp / (u32)MB; if (bb > 7u) bb = 7u;
        aoff[q] = bb * (u32)BSZ + (gp - bb * (u32)MB);
    }

    u32 a_base = (u32)(((((lane >> 4) << 3) + (lane & 7)) * 272)
                       + wm * 64 + ((lane >> 3) & 1) * 16);
    u32 b_off[4];
    #pragma unroll
    for (int q = 0; q < 4; q++) {
        int row = wn * 64 + q * 16 + ((lane >> 3) >> 1) * 8 + (lane & 7);
        b_off[q] = (u32)(row * 80 + ((lane >> 3) & 1) * 16);
    }

    float acc[2][8][4];
    #pragma unroll
    for (int mt = 0; mt < 2; mt++)
        #pragma unroll
        for (int nt = 0; nt < 8; nt++)
            #pragma unroll
            for (int q = 0; q < 4; q++) acc[mt][nt][q] = 0.f;

    auto stage = [&](int j, int buf) {
        int k0s = j * 32;
        // A: 32 k-rows x 256B = 1024 cpa8 (4/thread)
        #pragma unroll
        for (int q = 0; q < 4; q++) {
            u32 ka = g_ka[k0s + akk[q]];
            cpa8(AsB[buf] + adst[q], xg + ((u64)ka + aoff[q]) * 2);
        }
        // B: contiguous 8KB tile = 512 cpa16 (2/thread), fully coalesced
        u64 bt = wg + (u64)((u32)j * 32768u);
        #pragma unroll
        for (int q = 0; q < 2; q++) {
            int idx = tid + q * 256;
            int br = idx >> 2, bs = idx & 3;
            cpa16(BsB[buf] + (u32)(br * 80 + bs * 16), bt + (u32)(idx * 16));
        }
        cpa_commit();
    };

    stage(0, 0); stage(1, 1);

    int cur = 0, nxt = 2;
    for (int i = 0; i < 144; i++) {
        if (i + 2 < 144) { stage(i + 2, nxt); cpa_wait<2>(); }
        else if (i == 142) cpa_wait<1>();
        else               cpa_wait<0>();
        __syncthreads();

        #pragma unroll
        for (int sl = 0; sl < 2; sl++) {
            u32 af[2][4];
            #pragma unroll
            for (int mt = 0; mt < 2; mt++)
                ldsm4t(af[mt][0], af[mt][1], af[mt][2], af[mt][3],
                       AsB[cur] + a_base + (u32)(mt * 32) + (u32)(sl * 16 * 272));
            u32 bf[8][2];
            #pragma unroll
            for (int q = 0; q < 4; q++) {
                u32 r0, r1, r2, r3;
                ldsm4(r0, r1, r2, r3, BsB[cur] + b_off[q] + (u32)(sl * 32));
                bf[2 * q][0] = r0; bf[2 * q][1] = r1;
                bf[2 * q + 1][0] = r2; bf[2 * q + 1][1] = r3;
            }
            #pragma unroll
            for (int mt = 0; mt < 2; mt++)
                #pragma unroll
                for (int nt = 0; nt < 8; nt++)
                    mma_f16(acc[mt][nt], af[mt][0], af[mt][1], af[mt][2], af[mt][3],
                            bf[nt][0], bf[nt][1]);
        }
        __syncthreads();   // reads of buf cur done before it is re-staged
        cur = (cur == 2) ? 0 : cur + 1;
        nxt = (nxt == 2) ? 0 : nxt + 1;
    }

    // ---- epilogue: decode (b, p68) per row; store to g_y -------------------
    #pragma unroll
    for (int mt = 0; mt < 2; mt++) {
        u32 gpA = (u32)(p0 + wm * 32 + mt * 16 + g);
        u32 gpB = gpA + 8;
        u32 bA = gpA / (u32)MB, bB = gpB / (u32)MB;
        u32 pA = gpA - bA * (u32)MB, pB = gpB - bB * (u32)MB;
        bool okA = (bA < 8u) && (pA % (u32)PIT) < 66u;
        bool okB = (bB < 8u) && (pB % (u32)PIT) < 66u;
        #pragma unroll
        for (int nt = 0; nt < 8; nt++) {
            int o = o0 + wn * 64 + nt * 8 + 2 * tg;
            if (okA) {
                size_t ba = ((size_t)(bA * 512u + o)) * MB + pA;
                g_y[ba] = acc[mt][nt][0];
                g_y[ba + MB] = acc[mt][nt][1];
            }
            if (okB) {
                size_t bb = ((size_t)(bB * 512u + o)) * MB + pB;
                g_y[bb] = acc[mt][nt][2];
                g_y[bb + MB] = acc[mt][nt][3];
            }
        }
    }
}

// ---------------- K5: demod --------------------------------------------------
__global__ void k_demod() {
    int wid = (blockIdx.x * 256 + threadIdx.x) >> 5;
    int lane = threadIdx.x & 31;
    int b = wid >> 9, o = wid & 511;
    const float* Ao = g_A + o * 512;
    const float* sbp = g_s + b * 512;
    float acc = 0.f;
    #pragma unroll 4
    for (int i = lane; i < 512; i += 32) {
        float sv = sbp[i]; acc = fmaf(Ao[i], sv * sv, acc);
    }
    #pragma unroll
    for (int s = 16; s; s >>= 1) acc += __shfl_xor_sync(0xFFFFFFFFu, acc, s);
    if (lane == 0) g_d[wid] = rsqrtf(acc + 1e-8f);
}

// ---------------- K6: fir v2 — padded image, branch-free unrolled taps ------
#define FIR_SMEM ((24 + 5016 + 8 * 216 + 8832) * 4)   // 62400 B

__global__ __launch_bounds__(256) void k_fir(const float* __restrict__ upf,
                                             const float* __restrict__ dnf,
                                             const float* __restrict__ cb,
                                             float* __restrict__ out) {
    extern __shared__ float sm[];
    float* sfu   = sm;
    float* sfd   = sm + 12;
    float* simgp = sm + 24;            // 76 rows x 66 (rows 0-4, 71-75 zero)
    float* wbuf  = simgp + 5016;       // 8 * 216
    float* smid  = wbuf + 8 * 216;     // 138 x 64
    int blk = blockIdx.x;
    int tid = threadIdx.x;
    const float* src = g_y + (size_t)blk * MB;
    float dm = g_d[blk];
    float bias = cb[blk & 511];

    if (tid < 12) { sfu[tid] = 2.0f * upf[11 - tid]; sfd[tid] = dnf[11 - tid]; }
    for (int e = tid; e < 660; e += 256) {
        int r = e / 66, c = e - 66 * r;
        int row = (r < 5) ? r : r + 66;
        simgp[row * 66 + c] = 0.f;
    }
    for (int e = tid; e < NPIX; e += 256) {
        int r = e / 66, c = e - 66 * r;
        simgp[(r + 5) * 66 + c] = src[r * PIT + c] * dm + bias;
    }
    int warp = tid >> 5, lane = tid & 31;
    float* vrowp = wbuf + warp * 216;
    float* hrow  = vrowp + 78;
    if (lane < 5) { vrowp[lane] = 0.f; vrowp[71 + lane] = 0.f; }
    __syncthreads();

    for (int rr = warp; rr < SUP; rr += 8) {
        int tv0 = (rr & 1) ^ 1;
        int r0p = ((rr + tv0 - 9) >> 1) + 5;
        float c0 = sfu[tv0],     c1 = sfu[tv0 + 2], c2 = sfu[tv0 + 4];
        float c3 = sfu[tv0 + 6], c4 = sfu[tv0 + 8], c5 = sfu[tv0 + 10];
        for (int c = lane; c < 66; c += 32) {
            const float* sp = simgp + r0p * 66 + c;
            float a =      c0 * sp[0];
            a = fmaf(c1, sp[66],  a);
            a = fmaf(c2, sp[132], a);
            a = fmaf(c3, sp[198], a);
            a = fmaf(c4, sp[264], a);
            a = fmaf(c5, sp[330], a);
            vrowp[5 + c] = a;
        }
        __syncwarp();
        for (int q = lane; q < SUP; q += 32) {
            int tq0 = (q & 1) ^ 1;
            int q0p = ((q + tq0 - 9) >> 1) + 5;
            const float* vp = vrowp + q0p;
            float a =      sfu[tq0]      * vp[0];
            a = fmaf(sfu[tq0 + 2],  vp[1], a);
            a = fmaf(sfu[tq0 + 4],  vp[2], a);
            a = fmaf(sfu[tq0 + 6],  vp[3], a);
            a = fmaf(sfu[tq0 + 8],  vp[4], a);
            a = fmaf(sfu[tq0 + 10], vp[5], a);
            a = (a >= 0.f ? a : 0.2f * a) * 1.4142135623730951f;
            a = fminf(fmaxf(a, -256.f), 256.f);
            hrow[q] = a;
        }
        __syncwarp();
        for (int p2 = lane; p2 < 64; p2 += 32) {
            const float* hp = hrow + 2 * p2;
            float a = sfd[0] * hp[0];
            #pragma unroll
            for (int t = 1; t < 12; t++) a = fmaf(sfd[t], hp[t], a);
            smid[rr * 64 + p2] = a;
        }
        __syncwarp();
    }
    __syncthreads();

    float* dst = out + (size_t)blk * 4096;
    for (int e = tid; e < 4096; e += 256) {
        int p2 = e >> 6, c = e & 63;
        const float* mp = smid + 2 * p2 * 64 + c;
        float a = sfd[0] * mp[0];
        #pragma unroll
        for (int t = 1; t < 12; t++) a = fmaf(sfd[t], mp[t * 64], a);
        dst[e] = a;
    }
}

// ---------------- launch -----------------------------------------------------
extern "C" void kernel_launch(void* const* d_in, const int* in_sizes, int n_in,
                              void* d_out, int out_size) {
    const float* x  = (const float*)d_in[0];
    const float* w  = (const float*)d_in[1];
    const float* aw = (const float*)d_in[2];
    const float* ab = (const float*)d_in[3];
    const float* cw = (const float*)d_in[4];
    const float* cb = (const float*)d_in[5];
    const float* uf = (const float*)d_in[6];
    const float* df = (const float*)d_in[7];
    float* out = (float*)d_out;

    k_pre<<<1042, 256>>>(cw, w, aw, ab);            // 1 (wt + styles + ka)
    k_norm_styles<<<1, 256>>>();                    // 2

    dim3 pgrid(10, 512, BATCH);                     // 3 (one-pass pad, pitch 68)
    k_pad<<<pgrid, 256>>>(x);

    cudaFuncSetAttribute(k_conv, cudaFuncAttributeMaxDynamicSharedMemorySize, CONV_SMEM);
    dim3 cgrid(NTILES, 4);                          // 1124 blocks = 3.8 waves
    k_conv<<<cgrid, 256, CONV_SMEM>>>();            // 4 <-- profiled slot

    k_demod<<<512, 256>>>();                        // 5

    cudaFuncSetAttribute(k_fir, cudaFuncAttributeMaxDynamicSharedMemorySize, FIR_SMEM);
    k_fir<<<BATCH * CH, 256, FIR_SMEM>>>(uf, df, cb, out); // 6
}

// round 17
// speedup vs baseline: 1.5703x; 1.5703x over previous
#include <cuda_runtime.h>
#include <cuda_fp16.h>
#include <math.h>

#define BATCH 8
#define CH    512
#define NPIX  4356          // 66*66 valid pixels
#define MPAD  4752          // 66 rows * 72 padded cols
#define SUP   138
#define KTOT  4608
#define CISZ  5040          // per-ci padded image: 70 rows * 72 cols (halves)
#define BSZ   (512 * CISZ)  // per-batch padded image halves = 2,580,480

typedef unsigned int u32;
typedef unsigned long long u64;

// ---------------- scratch (device globals; zero-initialized) ----------------
__device__ float g_styles[BATCH * CH];
__device__ float g_s[BATCH * CH];
__device__ __align__(16) __half g_xp[3 * BATCH * (size_t)BSZ];    // 3 kx-shifted padded imgs
__device__ __align__(16) __half g_wtB[(size_t)CH * KTOT];         // half(wt) [o][k]
__device__ u32 g_ka[KTOT];                                        // k -> halves offset
__device__ float g_A[CH * CH];
__device__ float g_d[BATCH * CH];
__device__ __align__(16) float g_y[(size_t)BATCH * CH * MPAD];    // conv out [b][o][p']

__device__ __forceinline__ void ldsm4(u32& r0, u32& r1, u32& r2, u32& r3, u32 addr) {
    asm volatile("ldmatrix.sync.aligned.m8n8.x4.shared.b16 {%0,%1,%2,%3}, [%4];"
        : "=r"(r0), "=r"(r1), "=r"(r2), "=r"(r3) : "r"(addr));
}
__device__ __forceinline__ void ldsm4t(u32& r0, u32& r1, u32& r2, u32& r3, u32 addr) {
    asm volatile("ldmatrix.sync.aligned.m8n8.x4.trans.shared.b16 {%0,%1,%2,%3}, [%4];"
        : "=r"(r0), "=r"(r1), "=r"(r2), "=r"(r3) : "r"(addr));
}
__device__ __forceinline__ void mma_f16(float* c, u32 a0, u32 a1, u32 a2, u32 a3,
                                        u32 b0, u32 b1) {
    asm volatile("mma.sync.aligned.m16n8k16.row.col.f32.f16.f16.f32 "
        "{%0,%1,%2,%3}, {%4,%5,%6,%7}, {%8,%9}, {%0,%1,%2,%3};"
        : "+f"(c[0]), "+f"(c[1]), "+f"(c[2]), "+f"(c[3])
        : "r"(a0), "r"(a1), "r"(a2), "r"(a3), "r"(b0), "r"(b1));
}
__device__ __forceinline__ u32 smem_u32(const void* p) {
    u32 a; asm("{ .reg .u64 t; cvta.to.shared.u64 t, %1; cvt.u32.u64 %0, t; }"
               : "=r"(a) : "l"(p));
    return a;
}
__device__ __forceinline__ u64 gmem_u64(const void* p) {
    u64 a; asm("cvta.to.global.u64 %0, %1;" : "=l"(a) : "l"(p));
    return a;
}
__device__ __forceinline__ void cpa16(u32 dst, u64 src) {
    asm volatile("cp.async.cg.shared.global [%0], [%1], 16;"
                 :: "r"(dst), "l"(src) : "memory");
}
__device__ __forceinline__ void cpa_commit() {
    asm volatile("cp.async.commit_group;" ::: "memory");
}
template <int N> __device__ __forceinline__ void cpa_wait() {
    asm volatile("cp.async.wait_group %0;" :: "n"(N) : "memory");
}

// ---------------- K1 (merged): wt-normalize + styles + ka table -------------
__global__ void k_pre(const float* __restrict__ cw,
                      const float* __restrict__ w,
                      const float* __restrict__ aw,
                      const float* __restrict__ ab) {
    __shared__ float red[256];
    __shared__ float rsh;
    if (blockIdx.x < 512) {
        int o = blockIdx.x;
        const float* src = cw + (size_t)o * KTOT;
        float ss = 0.f;
        for (int e = threadIdx.x; e < KTOT; e += 256) {
            float v = src[e]; ss = fmaf(v, v, ss);
        }
        red[threadIdx.x] = ss; __syncthreads();
        for (int s = 128; s > 0; s >>= 1) {
            if (threadIdx.x < s) red[threadIdx.x] += red[threadIdx.x + s];
            __syncthreads();
        }
        if (threadIdx.x == 0) rsh = rsqrtf(red[0] * (1.0f / 4608.0f));
        __syncthreads();
        float r = rsh;
        for (int e = threadIdx.x; e < KTOT; e += 256)
            g_wtB[(size_t)o * KTOT + e] = __float2half_rn(src[e] * r);
        float r2 = r * r;
        for (int i = threadIdx.x; i < 512; i += 256) {
            float s9 = 0.f;
            #pragma unroll
            for (int k = 0; k < 9; k++) { float v = src[i * 9 + k]; s9 = fmaf(v, v, s9); }
            g_A[o * 512 + i] = s9 * r2;
        }
    } else if (blockIdx.x < 1024) {
        int wid = ((blockIdx.x - 512) * 256 + threadIdx.x) >> 5;
        int lane = threadIdx.x & 31;
        int b = wid >> 9, c = wid & 511;
        const float* wr = w + b * 512;
        const float* ar = aw + c * 512;
        float acc = 0.f;
        #pragma unroll 4
        for (int d = lane; d < 512; d += 32) acc = fmaf(wr[d], ar[d], acc);
        #pragma unroll
        for (int s = 16; s; s >>= 1) acc += __shfl_xor_sync(0xFFFFFFFFu, acc, s);
        if (lane == 0) g_styles[wid] = acc * 0.04419417382415922f + ab[c];
    } else {
        int k = (blockIdx.x - 1024) * 256 + threadIdx.x;
        if (k < KTOT) {
            int ci = k / 9; int t9 = k - 9 * ci;
            int ky = t9 / 3; int kx = t9 - 3 * ky;
            g_ka[k] = (u32)kx * (BATCH * (u32)BSZ) + (u32)(ci * CISZ + ky * 72);
        }
    }
}

// ---------------- K2: normalize styles --------------------------------------
__global__ void k_norm_styles() {
    __shared__ float red[256];
    float ss = 0.f;
    for (int i = threadIdx.x; i < 4096; i += 256) {
        float v = g_styles[i]; ss = fmaf(v, v, ss);
    }
    red[threadIdx.x] = ss; __syncthreads();
    for (int s = 128; s > 0; s >>= 1) {
        if (threadIdx.x < s) red[threadIdx.x] += red[threadIdx.x + s];
        __syncthreads();
    }
    float g = rsqrtf(red[0] * (1.0f / 4096.0f));
    for (int i = threadIdx.x; i < 4096; i += 256) g_s[i] = g_styles[i] * g;
}

// ---------------- K3: one-pass padded+scaled images, 3 kx shifts -------------
__global__ void k_pad(const float* __restrict__ x) {
    int i2 = blockIdx.x * 256 + threadIdx.x;       // < 2560, valid < 2520
    int ci = blockIdx.y, b = blockIdx.z;
    if (i2 >= 2520) return;
    int rr = i2 / 36;            // 0..69
    int cc = 2 * (i2 - rr * 36); // 0..70 even
    float s = g_s[b * 512 + ci];
    bool rok = (rr >= 2) & (rr < 66);
    float v0 = 0.f, v1 = 0.f;
    if (rok && cc < 64) {
        float2 xv = *(const float2*)&x[(((size_t)(b * 512 + ci)) * 64 + (rr - 2)) * 64 + cc];
        v0 = xv.x * s; v1 = xv.y * s;
    }
    float pv = 0.f;
    if (rok && cc > 0 && cc - 1 < 64)
        pv = x[(((size_t)(b * 512 + ci)) * 64 + (rr - 2)) * 64 + (cc - 1)] * s;
    float pv_sh = __shfl_up_sync(0xFFFFFFFFu, v1, 1);
    if ((threadIdx.x & 31) != 0) pv = pv_sh;

    __half2 pair  = __floats2half2_rn(v0, v1);
    __half2 pair1 = __floats2half2_rn(pv, v0);
    int j = 2 * i2;
    u32 base = (u32)(ci * CISZ + j);
    __half2* xp2 = (__half2*)g_xp;
    size_t b2 = ((size_t)b * BSZ) >> 1;
    size_t img = (size_t)BATCH * BSZ >> 1;
    xp2[2 * img + b2 + (base >> 1)] = pair;
    if (!(ci == 511 && i2 == 2519))
        xp2[b2 + ((base + 2) >> 1)] = pair;
    xp2[img + b2 + (base >> 1)] = pair1;
}

// ---------------- K4: pure-GEMM fp16 HMMA conv — exact R13 config ------------
#define ASTG 8704
#define BSTG 10240
#define CONV_SMEM (3 * (ASTG + BSTG))   // 56832

__global__ __launch_bounds__(256, 2) void k_conv() {
    extern __shared__ __align__(16) char dsm[];
    int tid = threadIdx.x, wid = tid >> 5, lane = tid & 31;
    int g = lane >> 2, tg = lane & 3;
    int wm = wid & 3, wn = wid >> 2;
    int b = blockIdx.z;
    int p0 = blockIdx.x * 128, o0 = blockIdx.y * 128;

    u32 sb = smem_u32(dsm);
    u32 AsB[3], BsB[3];
    #pragma unroll
    for (int s = 0; s < 3; s++) {
        AsB[s] = sb + s * ASTG;
        BsB[s] = sb + 3 * ASTG + s * BSTG;
    }
    u64 xpg = gmem_u64(g_xp) + ((u64)((u32)b * (u32)BSZ) + (u32)p0) * 2;
    u64 wg  = gmem_u64(g_wtB);

    u32 a_base = (u32)(((((lane >> 4) << 3) + (lane & 7)) * 272)
                       + wm * 64 + ((lane >> 3) & 1) * 16);
    u32 b_off[4];
    #pragma unroll
    for (int q = 0; q < 4; q++) {
        int row = wn * 64 + q * 16 + ((lane >> 3) >> 1) * 8 + (lane & 7);
        b_off[q] = (u32)(row * 80 + ((lane >> 3) & 1) * 16);
    }

    float acc[2][8][4];
    #pragma unroll
    for (int mt = 0; mt < 2; mt++)
        #pragma unroll
        for (int nt = 0; nt < 8; nt++)
            #pragma unroll
            for (int q = 0; q < 4; q++) acc[mt][nt][q] = 0.f;

    auto stage = [&](int j, int buf) {
        int k0s = j * 32;
        #pragma unroll
        for (int q = 0; q < 2; q++) {
            int idx = tid + q * 256;
            int kk = idx >> 4, seg = idx & 15;
            u32 ka = g_ka[k0s + kk];
            cpa16(AsB[buf] + (u32)(kk * 272 + seg * 16),
                  xpg + ((u64)ka + (u32)(seg * 8)) * 2);
        }
        #pragma unroll
        for (int q = 0; q < 2; q++) {
            int idx = tid + q * 256;
            int br = idx >> 2, bs = idx & 3;
            cpa16(BsB[buf] + (u32)(br * 80 + bs * 16),
                  wg + ((u64)(u32)(o0 + br) * KTOT + (u32)(k0s + bs * 8)) * 2);
        }
        cpa_commit();
    };

    stage(0, 0); stage(1, 1);

    int cur = 0, nxt = 2;
    for (int i = 0; i < 144; i++) {
        if (i + 2 < 144) { stage(i + 2, nxt); cpa_wait<2>(); }
        else if (i == 142) cpa_wait<1>();
        else               cpa_wait<0>();
        __syncthreads();

        #pragma unroll
        for (int sl = 0; sl < 2; sl++) {
            u32 af[2][4];
            #pragma unroll
            for (int mt = 0; mt < 2; mt++)
                ldsm4t(af[mt][0], af[mt][1], af[mt][2], af[mt][3],
                       AsB[cur] + a_base + (u32)(mt * 32) + (u32)(sl * 16 * 272));
            u32 bf[8][2];
            #pragma unroll
            for (int q = 0; q < 4; q++) {
                u32 r0, r1, r2, r3;
                ldsm4(r0, r1, r2, r3, BsB[cur] + b_off[q] + (u32)(sl * 32));
                bf[2 * q][0] = r0; bf[2 * q][1] = r1;
                bf[2 * q + 1][0] = r2; bf[2 * q + 1][1] = r3;
            }
            #pragma unroll
            for (int mt = 0; mt < 2; mt++)
                #pragma unroll
                for (int nt = 0; nt < 8; nt++)
                    mma_f16(acc[mt][nt], af[mt][0], af[mt][1], af[mt][2], af[mt][3],
                            bf[nt][0], bf[nt][1]);
        }
        __syncthreads();   // reads of buf cur done before it is re-staged
        cur = (cur == 2) ? 0 : cur + 1;
        nxt = (nxt == 2) ? 0 : nxt + 1;
    }

    // ---- epilogue: store to padded g_y ----
    #pragma unroll
    for (int mt = 0; mt < 2; mt++) {
        int pA = p0 + wm * 32 + mt * 16 + g;
        int pB = pA + 8;
        bool okA = (pA < MPAD) && (pA % 72) < 66;
        bool okB = (pB < MPAD) && (pB % 72) < 66;
        #pragma unroll
        for (int nt = 0; nt < 8; nt++) {
            int o = o0 + wn * 64 + nt * 8 + 2 * tg;
            size_t bo = ((size_t)(b * 512 + o)) * MPAD;
            if (okA) {
                g_y[bo + pA] = acc[mt][nt][0];
                g_y[bo + MPAD + pA] = acc[mt][nt][1];
            }
            if (okB) {
                g_y[bo + pB] = acc[mt][nt][2];
                g_y[bo + MPAD + pB] = acc[mt][nt][3];
            }
        }
    }
}

// ---------------- K5: demod --------------------------------------------------
__global__ void k_demod() {
    int wid = (blockIdx.x * 256 + threadIdx.x) >> 5;
    int lane = threadIdx.x & 31;
    int b = wid >> 9, o = wid & 511;
    const float* Ao = g_A + o * 512;
    const float* sbp = g_s + b * 512;
    float acc = 0.f;
    #pragma unroll 4
    for (int i = lane; i < 512; i += 32) {
        float sv = sbp[i]; acc = fmaf(Ao[i], sv * sv, acc);
    }
    #pragma unroll
    for (int s = 16; s; s >>= 1) acc += __shfl_xor_sync(0xFFFFFFFFu, acc, s);
    if (lane == 0) g_d[wid] = rsqrtf(acc + 1e-8f);
}

// ---------------- K6: fir v3 — he/ho split kills Hdown bank conflicts -------
// wbuf per warp (232 floats): vrowp[0..75] | he @78 (69) | ho @158 (69)
// (158-78) mod 32 == 16 -> even/odd Hup writes hit disjoint bank halves.
#define WSTR 232
#define FIR_SMEM ((24 + 5016 + 8 * WSTR + 8832) * 4)   // 62912 B

__global__ __launch_bounds__(256) void k_fir(const float* __restrict__ upf,
                                             const float* __restrict__ dnf,
                                             const float* __restrict__ cb,
                                             float* __restrict__ out) {
    extern __shared__ float sm[];
    float* sfu   = sm;
    float* sfd   = sm + 12;
    float* simgp = sm + 24;            // 76 rows x 66 (rows 0-4, 71-75 zero)
    float* wbuf  = simgp + 5016;       // 8 * WSTR
    float* smid  = wbuf + 8 * WSTR;    // 138 x 64
    int blk = blockIdx.x;
    int tid = threadIdx.x;
    const float* src = g_y + (size_t)blk * MPAD;
    float dm = g_d[blk];
    float bias = cb[blk & 511];

    if (tid < 12) { sfu[tid] = 2.0f * upf[11 - tid]; sfd[tid] = dnf[11 - tid]; }
    for (int e = tid; e < 660; e += 256) {
        int r = e / 66, c = e - 66 * r;
        int row = (r < 5) ? r : r + 66;
        simgp[row * 66 + c] = 0.f;
    }
    for (int e = tid; e < NPIX; e += 256) {
        int r = e / 66, c = e - 66 * r;
        simgp[(r + 5) * 66 + c] = src[r * 72 + c] * dm + bias;
    }
    int warp = tid >> 5, lane = tid & 31;
    float* vrowp = wbuf + warp * WSTR;
    float* he    = vrowp + 78;
    float* ho    = vrowp + 158;
    if (lane < 5) { vrowp[lane] = 0.f; vrowp[71 + lane] = 0.f; }
    __syncthreads();

    for (int rr = warp; rr < SUP; rr += 8) {
        int tv0 = (rr & 1) ^ 1;
        int r0p = ((rr + tv0 - 9) >> 1) + 5;
        float c0 = sfu[tv0],     c1 = sfu[tv0 + 2], c2 = sfu[tv0 + 4];
        float c3 = sfu[tv0 + 6], c4 = sfu[tv0 + 8], c5 = sfu[tv0 + 10];
        for (int c = lane; c < 66; c += 32) {
            const float* sp = simgp + r0p * 66 + c;
            float a =      c0 * sp[0];
            a = fmaf(c1, sp[66],  a);
            a = fmaf(c2, sp[132], a);
            a = fmaf(c3, sp[198], a);
            a = fmaf(c4, sp[264], a);
            a = fmaf(c5, sp[330], a);
            vrowp[5 + c] = a;
        }
        __syncwarp();
        for (int q = lane; q < SUP; q += 32) {
            int tq0 = (q & 1) ^ 1;
            int q0p = ((q + tq0 - 9) >> 1) + 5;
            const float* vp = vrowp + q0p;
            float a =      sfu[tq0]      * vp[0];
            a = fmaf(sfu[tq0 + 2],  vp[1], a);
            a = fmaf(sfu[tq0 + 4],  vp[2], a);
            a = fmaf(sfu[tq0 + 6],  vp[3], a);
            a = fmaf(sfu[tq0 + 8],  vp[4], a);
            a = fmaf(sfu[tq0 + 10], vp[5], a);
            a = (a >= 0.f ? a : 0.2f * a) * 1.4142135623730951f;
            a = fminf(fmaxf(a, -256.f), 256.f);
            if (q & 1) ho[q >> 1] = a; else he[q >> 1] = a;
        }
        __syncwarp();
        for (int p2 = lane; p2 < 64; p2 += 32) {
            const float* hep = he + p2;
            const float* hop = ho + p2;
            float a = sfd[0] * hep[0];
            a = fmaf(sfd[1],  hop[0], a);
            a = fmaf(sfd[2],  hep[1], a);
            a = fmaf(sfd[3],  hop[1], a);
            a = fmaf(sfd[4],  hep[2], a);
            a = fmaf(sfd[5],  hop[2], a);
            a = fmaf(sfd[6],  hep[3], a);
            a = fmaf(sfd[7],  hop[3], a);
            a = fmaf(sfd[8],  hep[4], a);
            a = fmaf(sfd[9],  hop[4], a);
            a = fmaf(sfd[10], hep[5], a);
            a = fmaf(sfd[11], hop[5], a);
            smid[rr * 64 + p2] = a;
        }
        __syncwarp();
    }
    __syncthreads();

    float* dst = out + (size_t)blk * 4096;
    for (int e = tid; e < 4096; e += 256) {
        int p2 = e >> 6, c = e & 63;
        const float* mp = smid + 2 * p2 * 64 + c;
        float a = sfd[0] * mp[0];
        #pragma unroll
        for (int t = 1; t < 12; t++) a = fmaf(sfd[t], mp[t * 64], a);
        dst[e] = a;
    }
}

// ---------------- launch -----------------------------------------------------
extern "C" void kernel_launch(void* const* d_in, const int* in_sizes, int n_in,
                              void* d_out, int out_size) {
    const float* x  = (const float*)d_in[0];
    const float* w  = (const float*)d_in[1];
    const float* aw = (const float*)d_in[2];
    const float* ab = (const float*)d_in[3];
    const float* cw = (const float*)d_in[4];
    const float* cb = (const float*)d_in[5];
    const float* uf = (const float*)d_in[6];
    const float* df = (const float*)d_in[7];
    float* out = (float*)d_out;

    k_pre<<<1042, 256>>>(cw, w, aw, ab);            // 1 (wt + styles + ka)
    k_norm_styles<<<1, 256>>>();                    // 2

    dim3 pgrid(10, 512, BATCH);                     // 3 (one-pass pad, pitch 72)
    k_pad<<<pgrid, 256>>>(x);

    cudaFuncSetAttribute(k_conv, cudaFuncAttributeMaxDynamicSharedMemorySize, CONV_SMEM);
    dim3 cgrid(38, 4, BATCH);
    k_conv<<<cgrid, 256, CONV_SMEM>>>();            // 4 <-- profiled slot

    k_demod<<<512, 256>>>();                        // 5

    cudaFuncSetAttribute(k_fir, cudaFuncAttributeMaxDynamicSharedMemorySize, FIR_SMEM);
    k_fir<<<BATCH * CH, 256, FIR_SMEM>>>(uf, df, cb, out); // 6
}